// round 11
// baseline (speedup 1.0000x reference)
#include <cuda_runtime.h>
#include <cstdint>

// Problem constants
#define BATCH 32
#define CIN   64
#define COUT  64
#define HH    112
#define WW    112
#define HW    (HH*WW)          // 12544
#define XS    80               // smem pixel / weight-row stride (bytes)

#define NTHREADS 512           // 8 IMMA warps + 8 dp4a warps
#define COLS_I   64            // IMMA cols [0,64), dp4a cols [64,112)
#define ROWS_PC  4             // output rows per CTA
#define TROWS    6             // input tile rows (4 + 2 halo)

// Repacked weights: [tap][cout][cin], tap = kh*3+kw, cin contiguous
__device__ __align__(16) int8_t g_wrep[9 * COUT * CIN];

// Inputs arrive as int32 (harness promotes int8 -> int32). Repack to int8.
__global__ void repack_w_kernel(const int* __restrict__ w) {
    int idx = blockIdx.x * blockDim.x + threadIdx.x;   // 36864
    if (idx < 9 * COUT * CIN) {
        int c   = idx & 63;
        int co  = (idx >> 6) & 63;
        int tap = idx >> 12;
        g_wrep[idx] = (int8_t)w[co * (CIN * 9) + c * 9 + tap];
    }
}

__device__ __forceinline__ void mma_s8(int* c, const uint32_t* a, uint32_t b0, uint32_t b1) {
    asm volatile(
        "mma.sync.aligned.m16n8k32.row.col.s32.s8.s8.s32 "
        "{%0,%1,%2,%3}, {%4,%5,%6,%7}, {%8,%9}, {%0,%1,%2,%3};\n"
        : "+r"(c[0]), "+r"(c[1]), "+r"(c[2]), "+r"(c[3])
        : "r"(a[0]), "r"(a[1]), "r"(a[2]), "r"(a[3]), "r"(b0), "r"(b1));
}

#define SX_BYTES (TROWS * 114 * XS)  // 54720
#define SW_BYTES (9 * COUT * XS)     // 46080
#define SB_BYTES 256                 // bias
#define SMEM_BYTES (SX_BYTES + SW_BYTES + SB_BYTES)   // 101056

__global__ __launch_bounds__(NTHREADS, 2)
void conv_int8_kernel(const int* __restrict__ x,
                      const float* __restrict__ wscale,
                      const float* __restrict__ ascale,
                      const float* __restrict__ bias,
                      float* __restrict__ out) {
    extern __shared__ int8_t smem[];
    int8_t* sx = smem;
    int8_t* sw = smem + SX_BYTES;
    float*  sb = reinterpret_cast<float*>(smem + SX_BYTES + SW_BYTES);

    const int tid = threadIdx.x;
    const int b   = blockIdx.y;
    const int h0  = blockIdx.x * ROWS_PC;   // 4 output rows per CTA

    // ---- zero halo cols 0/113 (loader writes zeros for OOB rows itself) ----
    for (int i = tid; i < TROWS * 2 * (XS / 4); i += NTHREADS) {
        int tr  = i / (2 * (XS / 4));
        int c2  = (i / (XS / 4)) & 1;          // 0 -> col 0, 1 -> col 113
        int wd  = i % (XS / 4);
        reinterpret_cast<uint32_t*>(sx + (tr * 114 + c2 * 113) * XS)[wd] = 0;
    }

    // ---- copy repacked weights + bias ----
    #pragma unroll
    for (int i = tid; i < 9 * COUT * 4; i += NTHREADS) {
        int row = i >> 2;
        reinterpret_cast<uint4*>(sw + row * XS)[i & 3] =
            reinterpret_cast<const uint4*>(g_wrep)[i];
    }
    if (tid < 64) sb[tid] = bias[tid];

    // ---- load input tile (int32 source), transpose to channel-contiguous int8 ----
    for (int i = tid; i < TROWS * 16 * 28; i += NTHREADS) {
        int w4 = i % 28;
        int c4 = (i / 28) & 15;
        int tr = i / (28 * 16);
        int gg = h0 - 1 + tr;
        uint4 u0 = {0,0,0,0}, u1 = {0,0,0,0}, u2 = {0,0,0,0}, u3 = {0,0,0,0};
        if ((unsigned)gg < (unsigned)HH) {
            const int* px = x + ((size_t)b * CIN + c4 * 4) * HW + gg * WW + w4 * 4;
            u0 = *reinterpret_cast<const uint4*>(px);
            u1 = *reinterpret_cast<const uint4*>(px + HW);
            u2 = *reinterpret_cast<const uint4*>(px + 2 * HW);
            u3 = *reinterpret_cast<const uint4*>(px + 3 * HW);
        }
        uint32_t p0[4] = {u0.x,u0.y,u0.z,u0.w}, p1[4] = {u1.x,u1.y,u1.z,u1.w},
                 p2[4] = {u2.x,u2.y,u2.z,u2.w}, p3[4] = {u3.x,u3.y,u3.z,u3.w};
        int8_t* dst = sx + (tr * 114 + 1 + w4 * 4) * XS + c4 * 4;
        #pragma unroll
        for (int j = 0; j < 4; ++j) {
            uint32_t r01 = __byte_perm(p0[j], p1[j], 0x0040);
            uint32_t r23 = __byte_perm(p2[j], p3[j], 0x0040);
            *reinterpret_cast<uint32_t*>(dst + j * XS) = __byte_perm(r01, r23, 0x5410);
        }
    }
    __syncthreads();

    const int lane  = tid & 31;
    const int warp  = tid >> 5;
    const float scale = wscale[0] * ascale[0];

    if (warp < 8) {
        // ====== IMMA warps: cols [0,64), warp = (cohalf x row), 2 passes x 32 px ======
        const int wm   = warp >> 2;              // cout half
        const int r    = warp & 3;               // output row within CTA (0..3)
        const int co0  = wm * 32;
        const int g4   = lane >> 2;              // 0..7
        const int q4   = (lane & 3) * 4;
        const int h    = h0 + r;

        #pragma unroll 1
        for (int pass = 0; pass < 2; ++pass) {
            const int colbase = pass * 32;

            int acc[2][4][4];
            #pragma unroll
            for (int mt = 0; mt < 2; ++mt)
                #pragma unroll
                for (int nt = 0; nt < 4; ++nt)
                    #pragma unroll
                    for (int k = 0; k < 4; ++k)
                        acc[mt][nt][k] = 0;

            #pragma unroll 1
            for (int tap = 0; tap < 9; ++tap) {
                const int8_t* sxp = sx + ((r + tap / 3) * 114 + colbase + (tap % 3)) * XS;
                const int8_t* swp = sw + tap * (COUT * XS) + (co0 + g4) * XS + q4;
                #pragma unroll
                for (int kh = 0; kh < 2; ++kh) {     // channels [0,32)/[32,64)
                    const int ko = kh * 32;
                    uint32_t a[2][4];
                    #pragma unroll
                    for (int mt = 0; mt < 2; ++mt) {
                        const int8_t* ap = swp + mt * 16 * XS + ko;
                        a[mt][0] = *reinterpret_cast<const uint32_t*>(ap);
                        a[mt][1] = *reinterpret_cast<const uint32_t*>(ap + 8 * XS);
                        a[mt][2] = *reinterpret_cast<const uint32_t*>(ap + 16);
                        a[mt][3] = *reinterpret_cast<const uint32_t*>(ap + 8 * XS + 16);
                    }
                    #pragma unroll
                    for (int nt = 0; nt < 4; ++nt) {
                        const int8_t* bp = sxp + (nt * 8 + g4) * XS + q4 + ko;
                        uint32_t b0 = *reinterpret_cast<const uint32_t*>(bp);
                        uint32_t b1 = *reinterpret_cast<const uint32_t*>(bp + 16);
                        mma_s8(acc[0][nt], a[0], b0, b1);
                        mma_s8(acc[1][nt], a[1], b0, b1);
                    }
                }
            }

            #pragma unroll
            for (int mt = 0; mt < 2; ++mt) {
                const int co_a = co0 + mt * 16 + g4;
                const int co_b = co_a + 8;
                const float ba = sb[co_a];
                const float bb = sb[co_b];
                float* oa = out + (((size_t)b * COUT + co_a) * HH + h) * WW + colbase + (lane & 3) * 2;
                float* ob = out + (((size_t)b * COUT + co_b) * HH + h) * WW + colbase + (lane & 3) * 2;
                #pragma unroll
                for (int nt = 0; nt < 4; ++nt) {
                    float2 va, vb;
                    va.x = (float)acc[mt][nt][0] * scale + ba;
                    va.y = (float)acc[mt][nt][1] * scale + ba;
                    vb.x = (float)acc[mt][nt][2] * scale + bb;
                    vb.y = (float)acc[mt][nt][3] * scale + bb;
                    *reinterpret_cast<float2*>(oa + nt * 8) = va;
                    *reinterpret_cast<float2*>(ob + nt * 8) = vb;
                }
            }
        }
    } else {
        // ====== dp4a warps: cols [64,112), warp = (cohalf x row), 2 passes x 24 px ======
        const int wid2   = warp - 8;             // 0..7
        const int r      = wid2 & 3;             // output row within CTA (0..3)
        const int cohalf = wid2 >> 2;            // cout half
        const int g      = lane >> 3;            // 0..3  (co offset)
        const int pj     = lane & 7;             // 0..7  (px group)
        const int co0d   = cohalf * 32 + g;      // thread co = co0d + 4*i
        const int h      = h0 + r;

        #pragma unroll 1
        for (int pass = 0; pass < 2; ++pass) {
            const int px0 = COLS_I + pass * 24 + pj;   // thread px = px0 + 8*j, j<3

            int acc[8][3];
            #pragma unroll
            for (int i = 0; i < 8; ++i)
                #pragma unroll
                for (int j = 0; j < 3; ++j)
                    acc[i][j] = 0;

            #pragma unroll 1
            for (int tap = 0; tap < 9; ++tap) {
                const int dh = tap / 3, dw = tap - dh * 3;
                const int8_t* xp = sx + ((r + dh) * 114 + px0 + dw) * XS;
                const int8_t* wp = sw + tap * (COUT * XS) + co0d * XS;
                #pragma unroll 4
                for (int kw = 0; kw < 8; ++kw) {      // int2: 2 k-words per load
                    int2 wv[8], xv[3];
                    #pragma unroll
                    for (int i = 0; i < 8; ++i)
                        wv[i] = *reinterpret_cast<const int2*>(wp + i * 4 * XS + kw * 8);
                    #pragma unroll
                    for (int j = 0; j < 3; ++j)
                        xv[j] = *reinterpret_cast<const int2*>(xp + j * 8 * XS + kw * 8);
                    #pragma unroll
                    for (int i = 0; i < 8; ++i)
                        #pragma unroll
                        for (int j = 0; j < 3; ++j) {
                            acc[i][j] = __dp4a(wv[i].x, xv[j].x, acc[i][j]);
                            acc[i][j] = __dp4a(wv[i].y, xv[j].y, acc[i][j]);
                        }
                }
            }

            #pragma unroll
            for (int i = 0; i < 8; ++i) {
                const int co = co0d + 4 * i;
                const float bc = sb[co];
                float* op = out + (((size_t)b * COUT + co) * HH + h) * WW;
                #pragma unroll
                for (int j = 0; j < 3; ++j)
                    op[px0 + 8 * j] = (float)acc[i][j] * scale + bc;
            }
        }
    }
}

extern "C" void kernel_launch(void* const* d_in, const int* in_sizes, int n_in,
                              void* d_out, int out_size) {
    const int*   x    = reinterpret_cast<const int*>(d_in[0]);
    const int*   w    = reinterpret_cast<const int*>(d_in[1]);
    const float* ws   = reinterpret_cast<const float*>(d_in[2]);
    const float* as   = reinterpret_cast<const float*>(d_in[3]);
    const float* bias = reinterpret_cast<const float*>(d_in[4]);
    float* out = reinterpret_cast<float*>(d_out);

    repack_w_kernel<<<(9 * COUT * CIN + 255) / 256, 256>>>(w);

    cudaFuncSetAttribute(conv_int8_kernel,
                         cudaFuncAttributeMaxDynamicSharedMemorySize, SMEM_BYTES);
    dim3 grid(HH / ROWS_PC, BATCH);   // 28 x 32 = 896 CTAs
    conv_int8_kernel<<<grid, NTHREADS, SMEM_BYTES>>>(x, ws, as, bias, out);
}

// round 12
// speedup vs baseline: 1.0512x; 1.0512x over previous
#include <cuda_runtime.h>
#include <cstdint>

// Problem constants
#define BATCH 32
#define CIN   64
#define COUT  64
#define HH    112
#define WW    112
#define HW    (HH*WW)          // 12544
#define XS    80               // smem pixel / weight-row stride (bytes)

#define NTHREADS 512           // 8 IMMA warps + 8 dp4a warps
#define COLS_I   64            // IMMA cols [0,64), dp4a cols [64,112)

// Repacked weights: [tap][cout][cin], tap = kh*3+kw, cin contiguous
__device__ __align__(16) int8_t g_wrep[9 * COUT * CIN];

// Inputs arrive as int32 (harness promotes int8 -> int32). Repack to int8.
__global__ void repack_w_kernel(const int* __restrict__ w) {
    int idx = blockIdx.x * blockDim.x + threadIdx.x;   // 36864
    if (idx < 9 * COUT * CIN) {
        int c   = idx & 63;
        int co  = (idx >> 6) & 63;
        int tap = idx >> 12;
        g_wrep[idx] = (int8_t)w[co * (CIN * 9) + c * 9 + tap];
    }
}

__device__ __forceinline__ void mma_s8(int* c, const uint32_t* a, uint32_t b0, uint32_t b1) {
    asm volatile(
        "mma.sync.aligned.m16n8k32.row.col.s32.s8.s8.s32 "
        "{%0,%1,%2,%3}, {%4,%5,%6,%7}, {%8,%9}, {%0,%1,%2,%3};\n"
        : "+r"(c[0]), "+r"(c[1]), "+r"(c[2]), "+r"(c[3])
        : "r"(a[0]), "r"(a[1]), "r"(a[2]), "r"(a[3]), "r"(b0), "r"(b1));
}

__device__ __forceinline__ int dp4a4(int4 a, int4 b, int acc) {
    acc = __dp4a(a.x, b.x, acc);
    acc = __dp4a(a.y, b.y, acc);
    acc = __dp4a(a.z, b.z, acc);
    acc = __dp4a(a.w, b.w, acc);
    return acc;
}

#define SX_BYTES (4 * 114 * XS)      // 36480
#define SW_BYTES (9 * COUT * XS)     // 46080
#define SB_BYTES 256                 // bias
#define SMEM_BYTES (SX_BYTES + SW_BYTES + SB_BYTES)

__global__ __launch_bounds__(NTHREADS, 2)
void conv_int8_kernel(const int* __restrict__ x,
                      const float* __restrict__ wscale,
                      const float* __restrict__ ascale,
                      const float* __restrict__ bias,
                      float* __restrict__ out) {
    extern __shared__ int8_t smem[];
    int8_t* sx = smem;
    int8_t* sw = smem + SX_BYTES;
    float*  sb = reinterpret_cast<float*>(smem + SX_BYTES + SW_BYTES);

    const int tid = threadIdx.x;
    const int b   = blockIdx.y;
    const int h0  = blockIdx.x * 2;      // 2 output rows per CTA

    // ---- zero halo cols 0/113 (loader writes zeros for OOB rows itself) ----
    for (int i = tid; i < 4 * 2 * (XS / 4); i += NTHREADS) {
        int tr  = i / (2 * (XS / 4));
        int c2  = (i / (XS / 4)) & 1;          // 0 -> col 0, 1 -> col 113
        int wd  = i % (XS / 4);
        reinterpret_cast<uint32_t*>(sx + (tr * 114 + c2 * 113) * XS)[wd] = 0;
    }

    // ---- copy repacked weights + bias ----
    #pragma unroll
    for (int i = tid; i < 9 * COUT * 4; i += NTHREADS) {
        int row = i >> 2;
        reinterpret_cast<uint4*>(sw + row * XS)[i & 3] =
            reinterpret_cast<const uint4*>(g_wrep)[i];
    }
    if (tid < 64) sb[tid] = bias[tid];

    // ---- load input tile (int32 source), transpose to channel-contiguous int8 ----
    for (int i = tid; i < 4 * 16 * 28; i += NTHREADS) {
        int w4 = i % 28;
        int c4 = (i / 28) & 15;
        int tr = i / (28 * 16);
        int gg = h0 - 1 + tr;
        uint4 u0 = {0,0,0,0}, u1 = {0,0,0,0}, u2 = {0,0,0,0}, u3 = {0,0,0,0};
        if ((unsigned)gg < (unsigned)HH) {
            const int* px = x + ((size_t)b * CIN + c4 * 4) * HW + gg * WW + w4 * 4;
            u0 = *reinterpret_cast<const uint4*>(px);
            u1 = *reinterpret_cast<const uint4*>(px + HW);
            u2 = *reinterpret_cast<const uint4*>(px + 2 * HW);
            u3 = *reinterpret_cast<const uint4*>(px + 3 * HW);
        }
        uint32_t p0[4] = {u0.x,u0.y,u0.z,u0.w}, p1[4] = {u1.x,u1.y,u1.z,u1.w},
                 p2[4] = {u2.x,u2.y,u2.z,u2.w}, p3[4] = {u3.x,u3.y,u3.z,u3.w};
        int8_t* dst = sx + (tr * 114 + 1 + w4 * 4) * XS + c4 * 4;
        #pragma unroll
        for (int j = 0; j < 4; ++j) {
            uint32_t r01 = __byte_perm(p0[j], p1[j], 0x0040);
            uint32_t r23 = __byte_perm(p2[j], p3[j], 0x0040);
            *reinterpret_cast<uint32_t*>(dst + j * XS) = __byte_perm(r01, r23, 0x5410);
        }
    }
    __syncthreads();

    const int lane  = tid & 31;
    const int warp  = tid >> 5;
    const float scale = wscale[0] * ascale[0];

    if (warp < 8) {
        // ================= IMMA warps: cols [0, 64) =================
        const int wm   = warp >> 2;              // cout half
        const int wn   = warp & 3;
        const int r    = wn >> 1;                // output row within CTA
        const int colbase = (wn & 1) * 32;       // 32-px column block
        const int co0  = wm * 32;
        const int g4   = lane >> 2;              // 0..7
        const int q4   = (lane & 3) * 4;

        int acc[2][4][4];
        #pragma unroll
        for (int mt = 0; mt < 2; ++mt)
            #pragma unroll
            for (int nt = 0; nt < 4; ++nt)
                #pragma unroll
                for (int k = 0; k < 4; ++k)
                    acc[mt][nt][k] = 0;

        #pragma unroll 1
        for (int tap = 0; tap < 9; ++tap) {
            const int8_t* sxp = sx + ((r + tap / 3) * 114 + colbase + (tap % 3)) * XS;
            const int8_t* swp = sw + tap * (COUT * XS) + (co0 + g4) * XS + q4;
            #pragma unroll
            for (int kh = 0; kh < 2; ++kh) {     // channels [0,32)/[32,64)
                const int ko = kh * 32;
                uint32_t a[2][4];
                #pragma unroll
                for (int mt = 0; mt < 2; ++mt) {
                    const int8_t* ap = swp + mt * 16 * XS + ko;
                    a[mt][0] = *reinterpret_cast<const uint32_t*>(ap);
                    a[mt][1] = *reinterpret_cast<const uint32_t*>(ap + 8 * XS);
                    a[mt][2] = *reinterpret_cast<const uint32_t*>(ap + 16);
                    a[mt][3] = *reinterpret_cast<const uint32_t*>(ap + 8 * XS + 16);
                }
                #pragma unroll
                for (int nt = 0; nt < 4; ++nt) {
                    const int8_t* bp = sxp + (nt * 8 + g4) * XS + q4 + ko;
                    uint32_t b0 = *reinterpret_cast<const uint32_t*>(bp);
                    uint32_t b1 = *reinterpret_cast<const uint32_t*>(bp + 16);
                    mma_s8(acc[0][nt], a[0], b0, b1);
                    mma_s8(acc[1][nt], a[1], b0, b1);
                }
            }
        }

        const int h = h0 + r;
        #pragma unroll
        for (int mt = 0; mt < 2; ++mt) {
            const int co_a = co0 + mt * 16 + g4;
            const int co_b = co_a + 8;
            const float ba = sb[co_a];
            const float bb = sb[co_b];
            float* oa = out + (((size_t)b * COUT + co_a) * HH + h) * WW + colbase + (lane & 3) * 2;
            float* ob = out + (((size_t)b * COUT + co_b) * HH + h) * WW + colbase + (lane & 3) * 2;
            #pragma unroll
            for (int nt = 0; nt < 4; ++nt) {
                float2 va, vb;
                va.x = (float)acc[mt][nt][0] * scale + ba;
                va.y = (float)acc[mt][nt][1] * scale + ba;
                vb.x = (float)acc[mt][nt][2] * scale + bb;
                vb.y = (float)acc[mt][nt][3] * scale + bb;
                *reinterpret_cast<float2*>(oa + nt * 8) = va;
                *reinterpret_cast<float2*>(ob + nt * 8) = vb;
            }
        }
    } else {
        // ====== dp4a warps: cols [64,112), int4 (16B) loads, 2 co-passes ======
        const int wid2   = warp - 8;             // 0..7
        const int r      = wid2 & 1;             // output row within CTA
        const int cohalf = (wid2 >> 1) & 1;      // cout half
        const int pxhalf = wid2 >> 2;            // 24-px block: [64,88) or [88,112)
        const int g      = lane >> 3;            // 0..3  (co offset)
        const int pj     = lane & 7;             // 0..7  (px group)
        const int px0    = COLS_I + pxhalf * 24 + pj;   // thread px = px0 + 8*j, j<3
        const int h      = h0 + r;

        #pragma unroll 1
        for (int cp = 0; cp < 2; ++cp) {         // co-pass: co = cobase + 4*i, i<4
            const int cobase = cohalf * 32 + cp * 16 + g;

            int acc[4][3];
            #pragma unroll
            for (int i = 0; i < 4; ++i)
                #pragma unroll
                for (int j = 0; j < 3; ++j)
                    acc[i][j] = 0;

            #pragma unroll 1
            for (int tap = 0; tap < 9; ++tap) {
                const int dh = tap / 3, dw = tap - dh * 3;
                const int8_t* xp = sx + ((r + dh) * 114 + px0 + dw) * XS;
                const int8_t* wp = sw + tap * (COUT * XS) + cobase * XS;
                #pragma unroll
                for (int kw = 0; kw < 4; ++kw) {      // int4: 4 k-words (16B) per load
                    int4 wv[4], xv[3];
                    #pragma unroll
                    for (int i = 0; i < 4; ++i)
                        wv[i] = *reinterpret_cast<const int4*>(wp + i * 4 * XS + kw * 16);
                    #pragma unroll
                    for (int j = 0; j < 3; ++j)
                        xv[j] = *reinterpret_cast<const int4*>(xp + j * 8 * XS + kw * 16);
                    #pragma unroll
                    for (int i = 0; i < 4; ++i)
                        #pragma unroll
                        for (int j = 0; j < 3; ++j)
                            acc[i][j] = dp4a4(wv[i], xv[j], acc[i][j]);
                }
            }

            #pragma unroll
            for (int i = 0; i < 4; ++i) {
                const int co = cobase + 4 * i;
                const float bc = sb[co];
                float* op = out + (((size_t)b * COUT + co) * HH + h) * WW;
                #pragma unroll
                for (int j = 0; j < 3; ++j)
                    op[px0 + 8 * j] = (float)acc[i][j] * scale + bc;
            }
        }
    }
}

extern "C" void kernel_launch(void* const* d_in, const int* in_sizes, int n_in,
                              void* d_out, int out_size) {
    const int*   x    = reinterpret_cast<const int*>(d_in[0]);
    const int*   w    = reinterpret_cast<const int*>(d_in[1]);
    const float* ws   = reinterpret_cast<const float*>(d_in[2]);
    const float* as   = reinterpret_cast<const float*>(d_in[3]);
    const float* bias = reinterpret_cast<const float*>(d_in[4]);
    float* out = reinterpret_cast<float*>(d_out);

    repack_w_kernel<<<(9 * COUT * CIN + 255) / 256, 256>>>(w);

    cudaFuncSetAttribute(conv_int8_kernel,
                         cudaFuncAttributeMaxDynamicSharedMemorySize, SMEM_BYTES);
    dim3 grid(HH / 2, BATCH);   // 56 x 32 = 1792 CTAs
    conv_int8_kernel<<<grid, NTHREADS, SMEM_BYTES>>>(x, ws, as, bias, out);
}